// round 7
// baseline (speedup 1.0000x reference)
#include <cuda_runtime.h>

// FlowComposite: flows [B,T,2,H,W] fp32 -> out [B,2,H,W] fp32.
// R7: warp-shuffle corner sharing. Each lane unconditionally gathers only its
// LEFT corners (xc0; 4 loads: 2 rows x 2 channels). The RIGHT corner (xc1)
// is served, in priority order: (1) xc1==xc0 (x-clamp) -> own value;
// (2) neighbor lane i+1's left corner via __shfl_down when its packed
// (row,col) matches (yc, xc1) -- the common smooth case; (3) predicated
// fallback gather (mismatch lanes + lane 31 only). Shared values are the
// identical global words the fallback would load -> bit-exact vs R2.
// Cuts unconditional gather requests 8 -> 4 per px/step (L1tex wavefronts
// are the binding pipe at 95%).

static constexpr int Bc = 8;
static constexpr int Tc = 12;
static constexpr int Hc = 544;
static constexpr int Wc = 960;
static constexpr int HW = Hc * Wc;

__global__ __launch_bounds__(256)
void flow_composite_kernel(const float* __restrict__ flows, float* __restrict__ out) {
    // 64x4 pixel tile per block; each warp = 32 consecutive x in one row.
    const int x = (blockIdx.x << 6) + (threadIdx.x & 63);
    const int y = (blockIdx.y << 2) + (threadIdx.x >> 6);
    const int b = blockIdx.z;
    const int lane = threadIdx.x & 31;
    const bool has_right = (lane != 31);

    const float xf = (float)x;
    const float yf = (float)y;

    const float* fb = flows + (unsigned)b * (Tc * 2 * HW);

    // ---- t = 0: u=v=0 exactly -> coherent loads, weights = 0.25 * validity.
    float u, v;
    {
        const float* f0 = fb;
        const float* f1 = fb + HW;

        const int xm = max(x - 1, 0);
        const int ym = max(y - 1, 0);
        const int r0 = ym * Wc;
        const int r1 = y * Wc;

        const float vx = (x >= 1) ? 1.0f : 0.0f;
        const float vy = (y >= 1) ? 1.0f : 0.0f;
        const float w00 = 0.25f * (vx * vy);
        const float w10 = 0.25f * vy;
        const float w01 = 0.25f * vx;
        const float w11 = 0.25f;

        const float a00 = __ldg(f0 + r0 + xm);
        const float a10 = __ldg(f0 + r0 + x);
        const float a01 = __ldg(f0 + r1 + xm);
        const float a11 = __ldg(f0 + r1 + x);
        const float b00 = __ldg(f1 + r0 + xm);
        const float b10 = __ldg(f1 + r0 + x);
        const float b01 = __ldg(f1 + r1 + xm);
        const float b11 = __ldg(f1 + r1 + x);

        u = ((w00 * a00 + w10 * a10) + w01 * a01) + w11 * a11;
        v = ((w00 * b00 + w10 * b10) + w01 * b01) + w11 * b11;
    }

    // ---- t = 1..11: divergent gather with shuffle corner sharing.
    #pragma unroll
    for (int t = 1; t < Tc; ++t) {
        const float* f0 = fb + (unsigned)t * (2 * HW);   // u plane
        const float* f1 = f0 + HW;                       // v plane

        const float px = xf + u - 0.5f;
        const float py = yf + v - 0.5f;

        const int x0 = __float2int_rd(px);
        const int y0 = __float2int_rd(py);

        const float wx1 = px - (float)x0;
        const float wy1 = py - (float)y0;
        const float wx0 = 1.0f - wx1;
        const float wy0 = 1.0f - wy1;

        const bool vx0 = (x0 >= 0) && (x0 <= Wc - 1);
        const bool vx1 = (x0 >= -1) && (x0 <= Wc - 2);
        const bool vy0 = (y0 >= 0) && (y0 <= Hc - 1);
        const bool vy1 = (y0 >= -1) && (y0 <= Hc - 2);

        const int xc0 = min(max(x0, 0), Wc - 1);
        const int xc1 = min(max(x0 + 1, 0), Wc - 1);
        const int yc0 = min(max(y0, 0), Hc - 1);
        const int yc1 = min(max(y0 + 1, 0), Hc - 1);

        const float w00 = wx0 * wy0 * ((vx0 && vy0) ? 1.0f : 0.0f);
        const float w10 = wx1 * wy0 * ((vx1 && vy0) ? 1.0f : 0.0f);
        const float w01 = wx0 * wy1 * ((vx0 && vy1) ? 1.0f : 0.0f);
        const float w11 = wx1 * wy1 * ((vx1 && vy1) ? 1.0f : 0.0f);

        const int r0 = yc0 * Wc;
        const int r1 = yc1 * Wc;

        // Unconditional gathers: LEFT corners only (4 requests).
        const float a00 = __ldg(f0 + r0 + xc0);
        const float a01 = __ldg(f0 + r1 + xc0);
        const float b00 = __ldg(f1 + r0 + xc0);
        const float b01 = __ldg(f1 + r1 + xc0);

        // Packed (row, col) identity of this lane's left-corner addresses.
        const int pack0 = (yc0 << 10) | xc0;
        const int pack1 = (yc1 << 10) | xc0;

        // Neighbor lane i+1's left-corner identity + values.
        const int   npack0 = __shfl_down_sync(0xffffffffu, pack0, 1);
        const int   npack1 = __shfl_down_sync(0xffffffffu, pack1, 1);
        const float na00   = __shfl_down_sync(0xffffffffu, a00, 1);
        const float na01   = __shfl_down_sync(0xffffffffu, a01, 1);
        const float nb00   = __shfl_down_sync(0xffffffffu, b00, 1);
        const float nb01   = __shfl_down_sync(0xffffffffu, b01, 1);

        const bool same_x = (xc1 == xc0);  // x-clamp (left or right edge)
        const bool ok0 = has_right && (npack0 == ((yc0 << 10) | xc1));
        const bool ok1 = has_right && (npack1 == ((yc1 << 10) | xc1));

        float a10 = same_x ? a00 : na00;
        float b10 = same_x ? b00 : nb00;
        if (!(same_x || ok0)) {            // fallback: rare mismatch lanes
            a10 = __ldg(f0 + r0 + xc1);
            b10 = __ldg(f1 + r0 + xc1);
        }

        float a11 = same_x ? a01 : na01;
        float b11 = same_x ? b01 : nb01;
        if (!(same_x || ok1)) {
            a11 = __ldg(f0 + r1 + xc1);
            b11 = __ldg(f1 + r1 + xc1);
        }

        // Same summation order as reference: ((c00 + c10) + c01) + c11
        const float s0 = ((w00 * a00 + w10 * a10) + w01 * a01) + w11 * a11;
        const float s1 = ((w00 * b00 + w10 * b10) + w01 * b01) + w11 * b11;

        u += s0;
        v += s1;
    }

    const int p = y * Wc + x;
    float* ob = out + (unsigned)b * (2 * HW);
    ob[p]      = u;
    ob[HW + p] = v;
}

extern "C" void kernel_launch(void* const* d_in, const int* in_sizes, int n_in,
                              void* d_out, int out_size) {
    const float* flows = (const float*)d_in[0];
    float* out = (float*)d_out;

    dim3 grid(Wc / 64, Hc / 4, Bc);   // exact cover, no tails
    dim3 block(256);
    flow_composite_kernel<<<grid, block>>>(flows, out);
}